// round 1
// baseline (speedup 1.0000x reference)
#include <cuda_runtime.h>
#include <cuda_bf16.h>
#include <math.h>

// Problem constants
#define BB 4
#define SS 4096
#define DD 512
#define MTOT (BB*SS)          // 16384 flattened rows

// GEMM tiling
#define Bb 128   // BM
#define Bn 128   // BN
#define Bk 16    // BK
#define TM 8
#define TN 8
#define NTHR 256
#define LDPAD 4
#define LDS_STRIDE (Bb + LDPAD)   // 132

// -------- scratch (device globals: allocation-free rule) --------
__device__ float g_q [MTOT * DD];
__device__ float g_qv[MTOT * DD];
__device__ float g_k [MTOT * DD];
__device__ float g_kv[MTOT * DD];
__device__ float g_out[MTOT * DD];
__device__ float g_attn[(size_t)BB * SS * SS];   // 256 MB scores

// ============================================================
// NT GEMM: C[M,N] = A[M,K] * B[N,K]^T (+ bias[N] if bias!=null)
// A,B row-major, K-major dot products. Optional batching via blockIdx.z.
// M,N divisible by 128; K divisible by 16.
// ============================================================
__global__ __launch_bounds__(NTHR, 2)
void gemm_nt(const float* __restrict__ A, const float* __restrict__ Bw,
             const float* __restrict__ bias, float* __restrict__ C,
             int M, int N, int K,
             long strideA, long strideB, long strideC)
{
    __shared__ float As[Bk][LDS_STRIDE];
    __shared__ float Bs[Bk][LDS_STRIDE];

    const int bz = blockIdx.z;
    A  += (long)bz * strideA;
    Bw += (long)bz * strideB;
    C  += (long)bz * strideC;

    const int m0 = blockIdx.y * Bb;
    const int n0 = blockIdx.x * Bn;
    const int tid = threadIdx.x;
    const int tx = tid & 15;        // 0..15 -> N micro
    const int ty = tid >> 4;        // 0..15 -> M micro

    // loader mapping: each thread loads 2x float4 from A and 2x float4 from B
    const int lr = tid >> 2;              // 0..63
    const int lk = (tid & 3) * 4;         // 0,4,8,12

    float acc[TM][TN];
    #pragma unroll
    for (int i = 0; i < TM; i++)
        #pragma unroll
        for (int j = 0; j < TN; j++) acc[i][j] = 0.f;

    for (int k0 = 0; k0 < K; k0 += Bk) {
        #pragma unroll
        for (int h = 0; h < 2; ++h) {
            const int row = lr + h * 64;
            float4 v = *(const float4*)(A + (long)(m0 + row) * K + k0 + lk);
            As[lk + 0][row] = v.x; As[lk + 1][row] = v.y;
            As[lk + 2][row] = v.z; As[lk + 3][row] = v.w;
            float4 w = *(const float4*)(Bw + (long)(n0 + row) * K + k0 + lk);
            Bs[lk + 0][row] = w.x; Bs[lk + 1][row] = w.y;
            Bs[lk + 2][row] = w.z; Bs[lk + 3][row] = w.w;
        }
        __syncthreads();

        #pragma unroll
        for (int k = 0; k < Bk; ++k) {
            float a[TM], b[TN];
            #pragma unroll
            for (int i = 0; i < TM; i++) a[i] = As[k][ty * TM + i];
            #pragma unroll
            for (int j = 0; j < TN; j++) b[j] = Bs[k][tx * TN + j];
            #pragma unroll
            for (int i = 0; i < TM; i++)
                #pragma unroll
                for (int j = 0; j < TN; j++)
                    acc[i][j] = fmaf(a[i], b[j], acc[i][j]);
        }
        __syncthreads();
    }

    float bv[TN];
    #pragma unroll
    for (int j = 0; j < TN; j++)
        bv[j] = bias ? bias[n0 + tx * TN + j] : 0.f;

    #pragma unroll
    for (int i = 0; i < TM; i++) {
        const int m = m0 + ty * TM + i;
        float* crow = C + (long)m * N + n0 + tx * TN;
        #pragma unroll
        for (int j = 0; j < TN; j += 4) {
            float4 v;
            v.x = acc[i][j + 0] + bv[j + 0];
            v.y = acc[i][j + 1] + bv[j + 1];
            v.z = acc[i][j + 2] + bv[j + 2];
            v.w = acc[i][j + 3] + bv[j + 3];
            *(float4*)(crow + j) = v;
        }
    }
}

// ============================================================
// NN GEMM with residual: C[M,N] = A[M,K] * B[K,N] + R[M,N]
// A,B,R,C row-major. Batched via blockIdx.z.
// ============================================================
__global__ __launch_bounds__(NTHR, 2)
void gemm_nn_res(const float* __restrict__ A, const float* __restrict__ Bm,
                 const float* __restrict__ R, float* __restrict__ C,
                 int M, int N, int K,
                 long strideA, long strideB, long strideR, long strideC)
{
    __shared__ float As[Bk][LDS_STRIDE];
    __shared__ float Bs[Bk][LDS_STRIDE];

    const int bz = blockIdx.z;
    A  += (long)bz * strideA;
    Bm += (long)bz * strideB;
    R  += (long)bz * strideR;
    C  += (long)bz * strideC;

    const int m0 = blockIdx.y * Bb;
    const int n0 = blockIdx.x * Bn;
    const int tid = threadIdx.x;
    const int tx = tid & 15;
    const int ty = tid >> 4;

    const int lr = tid >> 2;              // A loader: row 0..63
    const int lk = (tid & 3) * 4;         // A loader: k 0,4,8,12
    const int bk = tid >> 5;              // B loader: k row 0..7
    const int bn = (tid & 31) * 4;        // B loader: n 0..124

    float acc[TM][TN];
    #pragma unroll
    for (int i = 0; i < TM; i++)
        #pragma unroll
        for (int j = 0; j < TN; j++) acc[i][j] = 0.f;

    for (int k0 = 0; k0 < K; k0 += Bk) {
        #pragma unroll
        for (int h = 0; h < 2; ++h) {
            const int row = lr + h * 64;
            float4 v = *(const float4*)(A + (long)(m0 + row) * K + k0 + lk);
            As[lk + 0][row] = v.x; As[lk + 1][row] = v.y;
            As[lk + 2][row] = v.z; As[lk + 3][row] = v.w;
        }
        #pragma unroll
        for (int h = 0; h < 2; ++h) {
            const int kk = bk + h * 8;
            float4 v = *(const float4*)(Bm + (long)(k0 + kk) * N + n0 + bn);
            *(float4*)&Bs[kk][bn] = v;
        }
        __syncthreads();

        #pragma unroll
        for (int k = 0; k < Bk; ++k) {
            float a[TM], b[TN];
            #pragma unroll
            for (int i = 0; i < TM; i++) a[i] = As[k][ty * TM + i];
            #pragma unroll
            for (int j = 0; j < TN; j++) b[j] = Bs[k][tx * TN + j];
            #pragma unroll
            for (int i = 0; i < TM; i++)
                #pragma unroll
                for (int j = 0; j < TN; j++)
                    acc[i][j] = fmaf(a[i], b[j], acc[i][j]);
        }
        __syncthreads();
    }

    #pragma unroll
    for (int i = 0; i < TM; i++) {
        const int m = m0 + ty * TM + i;
        const float* rrow = R + (long)m * N + n0 + tx * TN;
        float* crow = C + (long)m * N + n0 + tx * TN;
        #pragma unroll
        for (int j = 0; j < TN; j += 4) {
            float4 r = *(const float4*)(rrow + j);
            float4 v;
            v.x = acc[i][j + 0] + r.x;
            v.y = acc[i][j + 1] + r.y;
            v.z = acc[i][j + 2] + r.z;
            v.w = acc[i][j + 3] + r.w;
            *(float4*)(crow + j) = v;
        }
    }
}

// ============================================================
// Row softmax over SS=4096 columns. One block (256 thr) per row.
// ============================================================
__global__ __launch_bounds__(256)
void softmax_rows(float* __restrict__ attn)
{
    float* p = attn + (size_t)blockIdx.x * SS;
    const int tid = threadIdx.x;

    float v[16];
    float mx = -INFINITY;
    #pragma unroll
    for (int i = 0; i < 16; i++) {
        v[i] = p[tid + i * 256];
        mx = fmaxf(mx, v[i]);
    }
    // block max
    __shared__ float red[8];
    #pragma unroll
    for (int o = 16; o; o >>= 1) mx = fmaxf(mx, __shfl_xor_sync(0xffffffffu, mx, o));
    if ((tid & 31) == 0) red[tid >> 5] = mx;
    __syncthreads();
    float m = red[0];
    #pragma unroll
    for (int i = 1; i < 8; i++) m = fmaxf(m, red[i]);
    __syncthreads();

    float s = 0.f;
    #pragma unroll
    for (int i = 0; i < 16; i++) {
        v[i] = __expf(v[i] - m);
        s += v[i];
    }
    #pragma unroll
    for (int o = 16; o; o >>= 1) s += __shfl_xor_sync(0xffffffffu, s, o);
    if ((tid & 31) == 0) red[tid >> 5] = s;
    __syncthreads();
    float tot = 0.f;
    #pragma unroll
    for (int i = 0; i < 8; i++) tot += red[i];
    const float inv = 1.f / tot;

    #pragma unroll
    for (int i = 0; i < 16; i++) p[tid + i * 256] = v[i] * inv;
}

// ============================================================
extern "C" void kernel_launch(void* const* d_in, const int* in_sizes, int n_in,
                              void* d_out, int out_size)
{
    const float* x   = (const float*)d_in[0];
    const float* y   = (const float*)d_in[1];
    const float* Wq  = (const float*)d_in[2];
    const float* bq  = (const float*)d_in[3];
    const float* Wqv = (const float*)d_in[4];
    const float* bqv = (const float*)d_in[5];
    const float* Wk  = (const float*)d_in[6];
    const float* bk  = (const float*)d_in[7];
    const float* Wkv = (const float*)d_in[8];
    const float* bkv = (const float*)d_in[9];
    const float* Wf  = (const float*)d_in[10];
    const float* bf  = (const float*)d_in[11];
    float* out = (float*)d_out;

    float *q, *qv, *k, *kv, *o, *attn;
    cudaGetSymbolAddress((void**)&q,    g_q);
    cudaGetSymbolAddress((void**)&qv,   g_qv);
    cudaGetSymbolAddress((void**)&k,    g_k);
    cudaGetSymbolAddress((void**)&kv,   g_kv);
    cudaGetSymbolAddress((void**)&o,    g_out);
    cudaGetSymbolAddress((void**)&attn, g_attn);

    dim3 thr(NTHR);

    // 1-4. projections: [16384,512] = [16384,512] x [512,512]^T
    {
        dim3 grid(DD / Bn, MTOT / Bb, 1);
        gemm_nt<<<grid, thr>>>(x, Wq,  bq,  q,  MTOT, DD, DD, 0, 0, 0);
        gemm_nt<<<grid, thr>>>(x, Wqv, bqv, qv, MTOT, DD, DD, 0, 0, 0);
        gemm_nt<<<grid, thr>>>(y, Wk,  bk,  k,  MTOT, DD, DD, 0, 0, 0);
        gemm_nt<<<grid, thr>>>(y, Wkv, bkv, kv, MTOT, DD, DD, 0, 0, 0);
    }

    // 5. scores = q @ k^T per batch: [4096,4096], K=512
    {
        dim3 grid(SS / Bn, SS / Bb, BB);
        gemm_nt<<<grid, thr>>>(q, k, nullptr, attn, SS, SS, DD,
                               (long)SS * DD, (long)SS * DD, (long)SS * SS);
    }

    // 6. softmax over rows
    softmax_rows<<<BB * SS, 256>>>(attn);

    // 7. out = attn @ kv + qv per batch: [4096,512], K=4096
    {
        dim3 grid(DD / Bn, SS / Bb, BB);
        gemm_nn_res<<<grid, thr>>>(attn, kv, qv, o, SS, DD, SS,
                                   (long)SS * SS, (long)SS * DD,
                                   (long)SS * DD, (long)SS * DD);
    }

    // 8. final = out @ Wf^T + bf: [16384,512]
    {
        dim3 grid(DD / Bn, MTOT / Bb, 1);
        gemm_nt<<<grid, thr>>>(o, Wf, bf, out, MTOT, DD, DD, 0, 0, 0);
    }
}

// round 8
// speedup vs baseline: 1.6051x; 1.6051x over previous
#include <cuda_runtime.h>
#include <cuda_bf16.h>
#include <math.h>
#include <stdint.h>

// Problem constants
#define BB 4
#define SS 4096
#define DD 512
#define MTOT (BB*SS)          // 16384 flattened rows

// Tiling
#define BM 128
#define BN 128
#define BK 32
#define NTHR 256              // 8 warps: 2 (M) x 4 (N), warp tile 64x32
#define SH 40                 // smem stride in halfs (80B rows) -> conflict-free
#define SHW 20                // stride in 32-bit words
#define TILE_H (BM * SH)      // 5120 halfs per tile
// per stage: Ahi, Alo, Bhi, Blo = 4 tiles; double buffered
#define STAGE_H (4 * TILE_H)
#define SMEM_BYTES (2 * STAGE_H * 2)   // 81920 bytes

// -------- scratch (device globals: allocation-free rule) --------
__device__ float g_q  [MTOT * DD];
__device__ float g_qv [MTOT * DD];
__device__ float g_k  [MTOT * DD];
__device__ float g_kvT[MTOT * DD];    // [B][D][S] transposed kv
__device__ float g_out[MTOT * DD];
__device__ float g_attn[(size_t)BB * SS * SS];   // 256 MB scores

// epilogue modes
#define MODE_BIAS   0   // C = acc + bias, normal layout
#define MODE_TBIAS  1   // C = acc + bias, transposed per-batch [D][S] layout
#define MODE_PLAIN  2   // C = acc
#define MODE_RES    3   // C = acc + R, normal layout

__device__ __forceinline__ void mma_bf16(float c[4],
                                         uint32_t a0, uint32_t a1, uint32_t a2, uint32_t a3,
                                         uint32_t b0, uint32_t b1) {
    asm volatile(
        "mma.sync.aligned.m16n8k16.row.col.f32.bf16.bf16.f32 "
        "{%0,%1,%2,%3}, {%4,%5,%6,%7}, {%8,%9}, {%0,%1,%2,%3};\n"
        : "+f"(c[0]), "+f"(c[1]), "+f"(c[2]), "+f"(c[3])
        : "r"(a0), "r"(a1), "r"(a2), "r"(a3), "r"(b0), "r"(b1));
}

// split fp32x4 -> (hi word pair, lo word pair); word = [k even | k odd<<16]
__device__ __forceinline__ void split4(float4 v, uint2& wh, uint2& wl) {
    __nv_bfloat16 h0 = __float2bfloat16_rn(v.x);
    __nv_bfloat16 h1 = __float2bfloat16_rn(v.y);
    __nv_bfloat16 h2 = __float2bfloat16_rn(v.z);
    __nv_bfloat16 h3 = __float2bfloat16_rn(v.w);
    __nv_bfloat16 l0 = __float2bfloat16_rn(v.x - __bfloat162float(h0));
    __nv_bfloat16 l1 = __float2bfloat16_rn(v.y - __bfloat162float(h1));
    __nv_bfloat16 l2 = __float2bfloat16_rn(v.z - __bfloat162float(h2));
    __nv_bfloat16 l3 = __float2bfloat16_rn(v.w - __bfloat162float(h3));
    __nv_bfloat162 ph0 = {h0, h1}, ph1 = {h2, h3};
    __nv_bfloat162 pl0 = {l0, l1}, pl1 = {l2, l3};
    wh.x = *(uint32_t*)&ph0; wh.y = *(uint32_t*)&ph1;
    wl.x = *(uint32_t*)&pl0; wl.y = *(uint32_t*)&pl1;
}

// ============================================================
// NT bf16x3 tensor-core GEMM: C[M,N] = A[M,K] * B[N,K]^T
// All operands fp32 in gmem; split to bf16 hi/lo in smem.
// Batched via blockIdx.z. M,N %128==0, K %32==0.
// ============================================================
template <int MODE>
__global__ __launch_bounds__(NTHR, 1)
void mma_nt3(const float* __restrict__ A, const float* __restrict__ Bw,
             const float* __restrict__ aux,     // bias (MODE_BIAS/TBIAS) or R (MODE_RES)
             float* __restrict__ C,
             int M, int N, int K,
             long strideA, long strideB, long strideAux, long strideC)
{
    extern __shared__ uint16_t sm[];
    const int bz = blockIdx.z;
    A   += (long)bz * strideA;
    Bw  += (long)bz * strideB;
    C   += (long)bz * strideC;
    const float* R = aux ? aux + (long)bz * strideAux : (const float*)0;

    const int m0 = blockIdx.y * BM;
    const int n0 = blockIdx.x * BN;
    const int tid  = threadIdx.x;
    const int wid  = tid >> 5;
    const int lane = tid & 31;
    const int g = lane >> 2;       // 0..7
    const int t = lane & 3;        // 0..3
    const int warp_m = wid & 1;    // 0..1
    const int warp_n = wid >> 1;   // 0..3

    // loader indices (A and B tiles are both 128 rows x 32 k)
    const int lrow = tid >> 3;        // 0..31 (+ i*32)
    const int lc4  = (tid & 7) * 4;   // k offset 0,4,..28

    float acc[4][4][4];
    #pragma unroll
    for (int mf = 0; mf < 4; mf++)
        #pragma unroll
        for (int nf = 0; nf < 4; nf++)
            #pragma unroll
            for (int r = 0; r < 4; r++) acc[mf][nf][r] = 0.f;

    float4 pa[4], pb[4];

    // smem tile bases (in halfs) per stage
    // stage s: Ahi = s*STAGE_H, Alo = +TILE_H, Bhi = +2*TILE_H, Blo = +3*TILE_H
    #define ST_AHI(s) (sm + (s) * STAGE_H)
    #define ST_ALO(s) (sm + (s) * STAGE_H + TILE_H)
    #define ST_BHI(s) (sm + (s) * STAGE_H + 2 * TILE_H)
    #define ST_BLO(s) (sm + (s) * STAGE_H + 3 * TILE_H)

    // prefetch tile 0
    #pragma unroll
    for (int i = 0; i < 4; i++) {
        int row = lrow + i * 32;
        pa[i] = *(const float4*)(A  + (long)(m0 + row) * K + lc4);
        pb[i] = *(const float4*)(Bw + (long)(n0 + row) * K + lc4);
    }
    #pragma unroll
    for (int i = 0; i < 4; i++) {
        int row = lrow + i * 32;
        uint2 wh, wl;
        split4(pa[i], wh, wl);
        *(uint2*)(ST_AHI(0) + row * SH + lc4) = wh;
        *(uint2*)(ST_ALO(0) + row * SH + lc4) = wl;
        split4(pb[i], wh, wl);
        *(uint2*)(ST_BHI(0) + row * SH + lc4) = wh;
        *(uint2*)(ST_BLO(0) + row * SH + lc4) = wl;
    }

    const int KT = K / BK;
    int buf = 0;
    for (int kt = 0; kt < KT; kt++) {
        __syncthreads();
        if (kt + 1 < KT) {
            const int k0 = (kt + 1) * BK;
            #pragma unroll
            for (int i = 0; i < 4; i++) {
                int row = lrow + i * 32;
                pa[i] = *(const float4*)(A  + (long)(m0 + row) * K + k0 + lc4);
                pb[i] = *(const float4*)(Bw + (long)(n0 + row) * K + k0 + lc4);
            }
        }

        const uint32_t* Ah = (const uint32_t*)ST_AHI(buf) + (warp_m * 64) * SHW;
        const uint32_t* Al = (const uint32_t*)ST_ALO(buf) + (warp_m * 64) * SHW;
        const uint32_t* Bh = (const uint32_t*)ST_BHI(buf) + (warp_n * 32) * SHW;
        const uint32_t* Bl = (const uint32_t*)ST_BLO(buf) + (warp_n * 32) * SHW;

        #pragma unroll
        for (int ks = 0; ks < 2; ks++) {          // two k16 steps per BK=32
            const int kw = ks * 8;                // word offset
            uint32_t ah[4][4], al[4][4], bh[4][2], bl[4][2];
            #pragma unroll
            for (int mf = 0; mf < 4; mf++) {
                const int r = (mf * 16 + g) * SHW + kw + t;
                ah[mf][0] = Ah[r];
                ah[mf][1] = Ah[r + 8 * SHW];
                ah[mf][2] = Ah[r + 4];
                ah[mf][3] = Ah[r + 8 * SHW + 4];
                al[mf][0] = Al[r];
                al[mf][1] = Al[r + 8 * SHW];
                al[mf][2] = Al[r + 4];
                al[mf][3] = Al[r + 8 * SHW + 4];
            }
            #pragma unroll
            for (int nf = 0; nf < 4; nf++) {
                const int r = (nf * 8 + g) * SHW + kw + t;
                bh[nf][0] = Bh[r];
                bh[nf][1] = Bh[r + 4];
                bl[nf][0] = Bl[r];
                bl[nf][1] = Bl[r + 4];
            }
            #pragma unroll
            for (int mf = 0; mf < 4; mf++)
                #pragma unroll
                for (int nf = 0; nf < 4; nf++) {
                    mma_bf16(acc[mf][nf], ah[mf][0], ah[mf][1], ah[mf][2], ah[mf][3],
                             bh[nf][0], bh[nf][1]);
                    mma_bf16(acc[mf][nf], ah[mf][0], ah[mf][1], ah[mf][2], ah[mf][3],
                             bl[nf][0], bl[nf][1]);
                    mma_bf16(acc[mf][nf], al[mf][0], al[mf][1], al[mf][2], al[mf][3],
                             bh[nf][0], bh[nf][1]);
                }
        }

        if (kt + 1 < KT) {
            buf ^= 1;
            #pragma unroll
            for (int i = 0; i < 4; i++) {
                int row = lrow + i * 32;
                uint2 wh, wl;
                split4(pa[i], wh, wl);
                *(uint2*)(ST_AHI(buf) + row * SH + lc4) = wh;
                *(uint2*)(ST_ALO(buf) + row * SH + lc4) = wl;
                split4(pb[i], wh, wl);
                *(uint2*)(ST_BHI(buf) + row * SH + lc4) = wh;
                *(uint2*)(ST_BLO(buf) + row * SH + lc4) = wl;
            }
        }
    }

    // ---------------- epilogue ----------------
    if (MODE == MODE_TBIAS) {
        // transposed per-batch store: Ct[b][col][s], s = row within batch
        const long cbase = (long)(m0 >> 12) * DD * SS;
        const int  s0    = (m0 & (SS - 1)) + warp_m * 64;
        #pragma unroll
        for (int nf = 0; nf < 4; nf++) {
            const int col = warp_n * 32 + nf * 8 + t * 2;
            const float b0 = aux[n0 + col];
            const float b1 = aux[n0 + col + 1];
            #pragma unroll
            for (int mf = 0; mf < 4; mf++) {
                const int srow = s0 + mf * 16 + g;
                float* c0 = C + cbase + (long)(n0 + col) * SS + srow;
                float* c1 = C + cbase + (long)(n0 + col + 1) * SS + srow;
                c0[0] = acc[mf][nf][0] + b0;
                c1[0] = acc[mf][nf][1] + b1;
                c0[8] = acc[mf][nf][2] + b0;
                c1[8] = acc[mf][nf][3] + b1;
            }
        }
    } else {
        #pragma unroll
        for (int nf = 0; nf < 4; nf++) {
            const int col = n0 + warp_n * 32 + nf * 8 + t * 2;
            float b0 = 0.f, b1 = 0.f;
            if (MODE == MODE_BIAS) { b0 = aux[col]; b1 = aux[col + 1]; }
            #pragma unroll
            for (int mf = 0; mf < 4; mf++) {
                const int row0 = m0 + warp_m * 64 + mf * 16 + g;
                float r00 = b0, r01 = b1, r10 = b0, r11 = b1;
                if (MODE == MODE_RES) {
                    float2 r0 = *(const float2*)(R + (long)row0 * N + col);
                    float2 r1 = *(const float2*)(R + (long)(row0 + 8) * N + col);
                    r00 = r0.x; r01 = r0.y; r10 = r1.x; r11 = r1.y;
                }
                float2 v0 = make_float2(acc[mf][nf][0] + r00, acc[mf][nf][1] + r01);
                float2 v1 = make_float2(acc[mf][nf][2] + r10, acc[mf][nf][3] + r11);
                *(float2*)(C + (long)row0 * N + col)       = v0;
                *(float2*)(C + (long)(row0 + 8) * N + col) = v1;
            }
        }
    }
}

// ============================================================
// Row softmax over SS=4096 columns. One block (256 thr) per row.
// ============================================================
__global__ __launch_bounds__(256)
void softmax_rows(float* __restrict__ attn)
{
    float* p = attn + (size_t)blockIdx.x * SS;
    const int tid = threadIdx.x;

    float4 v[4];
    float mx = -INFINITY;
    #pragma unroll
    for (int i = 0; i < 4; i++) {
        v[i] = *(float4*)(p + (tid + i * 256) * 4);
        mx = fmaxf(fmaxf(fmaxf(v[i].x, v[i].y), fmaxf(v[i].z, v[i].w)), mx);
    }
    __shared__ float red[8];
    #pragma unroll
    for (int o = 16; o; o >>= 1) mx = fmaxf(mx, __shfl_xor_sync(0xffffffffu, mx, o));
    if ((tid & 31) == 0) red[tid >> 5] = mx;
    __syncthreads();
    float m = red[0];
    #pragma unroll
    for (int i = 1; i < 8; i++) m = fmaxf(m, red[i]);
    __syncthreads();

    float s = 0.f;
    #pragma unroll
    for (int i = 0; i < 4; i++) {
        v[i].x = __expf(v[i].x - m); v[i].y = __expf(v[i].y - m);
        v[i].z = __expf(v[i].z - m); v[i].w = __expf(v[i].w - m);
        s += v[i].x + v[i].y + v[i].z + v[i].w;
    }
    #pragma unroll
    for (int o = 16; o; o >>= 1) s += __shfl_xor_sync(0xffffffffu, s, o);
    if ((tid & 31) == 0) red[tid >> 5] = s;
    __syncthreads();
    float tot = 0.f;
    #pragma unroll
    for (int i = 0; i < 8; i++) tot += red[i];
    const float inv = 1.f / tot;

    #pragma unroll
    for (int i = 0; i < 4; i++) {
        v[i].x *= inv; v[i].y *= inv; v[i].z *= inv; v[i].w *= inv;
        *(float4*)(p + (tid + i * 256) * 4) = v[i];
    }
}

// ============================================================
extern "C" void kernel_launch(void* const* d_in, const int* in_sizes, int n_in,
                              void* d_out, int out_size)
{
    const float* x   = (const float*)d_in[0];
    const float* y   = (const float*)d_in[1];
    const float* Wq  = (const float*)d_in[2];
    const float* bq  = (const float*)d_in[3];
    const float* Wqv = (const float*)d_in[4];
    const float* bqv = (const float*)d_in[5];
    const float* Wk  = (const float*)d_in[6];
    const float* bk  = (const float*)d_in[7];
    const float* Wkv = (const float*)d_in[8];
    const float* bkv = (const float*)d_in[9];
    const float* Wf  = (const float*)d_in[10];
    const float* bf  = (const float*)d_in[11];
    float* out = (float*)d_out;

    float *q, *qv, *k, *kvT, *o, *attn;
    cudaGetSymbolAddress((void**)&q,    g_q);
    cudaGetSymbolAddress((void**)&qv,   g_qv);
    cudaGetSymbolAddress((void**)&k,    g_k);
    cudaGetSymbolAddress((void**)&kvT,  g_kvT);
    cudaGetSymbolAddress((void**)&o,    g_out);
    cudaGetSymbolAddress((void**)&attn, g_attn);

    cudaFuncSetAttribute(mma_nt3<MODE_BIAS>,  cudaFuncAttributeMaxDynamicSharedMemorySize, SMEM_BYTES);
    cudaFuncSetAttribute(mma_nt3<MODE_TBIAS>, cudaFuncAttributeMaxDynamicSharedMemorySize, SMEM_BYTES);
    cudaFuncSetAttribute(mma_nt3<MODE_PLAIN>, cudaFuncAttributeMaxDynamicSharedMemorySize, SMEM_BYTES);
    cudaFuncSetAttribute(mma_nt3<MODE_RES>,   cudaFuncAttributeMaxDynamicSharedMemorySize, SMEM_BYTES);

    dim3 thr(NTHR);

    // 1-4. projections: [16384,512] = [16384,512] x [512,512]^T
    {
        dim3 grid(DD / BN, MTOT / BM, 1);
        mma_nt3<MODE_BIAS> <<<grid, thr, SMEM_BYTES>>>(x, Wq,  bq,  q,   MTOT, DD, DD, 0, 0, 0, 0);
        mma_nt3<MODE_BIAS> <<<grid, thr, SMEM_BYTES>>>(x, Wqv, bqv, qv,  MTOT, DD, DD, 0, 0, 0, 0);
        mma_nt3<MODE_BIAS> <<<grid, thr, SMEM_BYTES>>>(y, Wk,  bk,  k,   MTOT, DD, DD, 0, 0, 0, 0);
        mma_nt3<MODE_TBIAS><<<grid, thr, SMEM_BYTES>>>(y, Wkv, bkv, kvT, MTOT, DD, DD, 0, 0, 0, 0);
    }

    // 5. scores = q @ k^T per batch: [4096,4096], K=512
    {
        dim3 grid(SS / BN, SS / BM, BB);
        mma_nt3<MODE_PLAIN><<<grid, thr, SMEM_BYTES>>>(q, k, nullptr, attn, SS, SS, DD,
                                                       (long)SS * DD, (long)SS * DD, 0, (long)SS * SS);
    }

    // 6. softmax over rows
    softmax_rows<<<BB * SS, 256>>>(attn);

    // 7. o = attn @ kvT^T + qv per batch: [4096,512], K=4096  (NT form!)
    {
        dim3 grid(DD / BN, SS / BM, BB);
        mma_nt3<MODE_RES><<<grid, thr, SMEM_BYTES>>>(attn, kvT, qv, o, SS, DD, SS,
                                                     (long)SS * SS, (long)DD * SS,
                                                     (long)SS * DD, (long)SS * DD);
    }

    // 8. final = o @ Wf^T + bf: [16384,512]
    {
        dim3 grid(DD / BN, MTOT / BM, 1);
        mma_nt3<MODE_BIAS><<<grid, thr, SMEM_BYTES>>>(o, Wf, bf, out, MTOT, DD, DD, 0, 0, 0, 0);
    }
}

// round 10
// speedup vs baseline: 2.1753x; 1.3552x over previous
#include <cuda_runtime.h>
#include <cuda_bf16.h>
#include <math.h>
#include <stdint.h>

// Problem constants
#define BB 4
#define SS 4096
#define DD 512
#define MTOT (BB*SS)          // 16384 flattened rows

// Tiling
#define BM 128
#define BN 128
#define BK 32
#define NTHR 256              // 8 warps: 2 (M) x 4 (N), warp tile 64x32

// smem: unpadded bf16 tiles 128 rows x 32 cols = 64B/row, XOR-swizzled chunks
#define TILE_B   (128 * 64)       // 8192 bytes
#define STAGE_B  (4 * TILE_B)     // Ahi, Alo, Bhi, Blo = 32768
#define SMEM_BYTES (2 * STAGE_B)  // 65536

// swizzled byte offset of 16B chunk (row, c), c = k-chunk 0..3
#define SWZ(row, c) ((uint32_t)((row) * 64 + ((((c) ^ (((row) >> 1) & 3))) << 4)))

// epilogue modes
#define MODE_BIAS   0
#define MODE_TBIAS  1
#define MODE_PLAIN  2
#define MODE_RES    3

// -------- scratch (device globals: allocation-free rule) --------
__device__ float g_q  [MTOT * DD];
__device__ float g_qv [MTOT * DD];
__device__ float g_k  [MTOT * DD];
__device__ float g_kvT[MTOT * DD];    // [B][D][S] transposed kv
__device__ float g_out[MTOT * DD];
__device__ float g_attn[(size_t)BB * SS * SS];   // 256 MB scores

__device__ __forceinline__ uint32_t smem_u32(const void* p) {
    uint32_t a;
    asm("{ .reg .u64 t; cvta.to.shared.u64 t, %1; cvt.u32.u64 %0, t; }"
        : "=r"(a) : "l"(p));
    return a;
}

__device__ __forceinline__ void mma_bf16(float c[4],
                                         uint32_t a0, uint32_t a1, uint32_t a2, uint32_t a3,
                                         uint32_t b0, uint32_t b1) {
    asm volatile(
        "mma.sync.aligned.m16n8k16.row.col.f32.bf16.bf16.f32 "
        "{%0,%1,%2,%3}, {%4,%5,%6,%7}, {%8,%9}, {%0,%1,%2,%3};\n"
        : "+f"(c[0]), "+f"(c[1]), "+f"(c[2]), "+f"(c[3])
        : "r"(a0), "r"(a1), "r"(a2), "r"(a3), "r"(b0), "r"(b1));
}

__device__ __forceinline__ void ldsm4(uint32_t& r0, uint32_t& r1, uint32_t& r2, uint32_t& r3,
                                      uint32_t addr) {
    asm volatile("ldmatrix.sync.aligned.m8n8.x4.shared.b16 {%0,%1,%2,%3}, [%4];"
                 : "=r"(r0), "=r"(r1), "=r"(r2), "=r"(r3) : "r"(addr));
}

// split 2 fp32 -> packed bf16 hi word, return residuals
__device__ __forceinline__ uint32_t pack_hi2(float a, float b, float& ra, float& rb) {
    __nv_bfloat162 h;
    h.x = __float2bfloat16_rn(a);
    h.y = __float2bfloat16_rn(b);
    ra = a - __bfloat162float(h.x);
    rb = b - __bfloat162float(h.y);
    return *(uint32_t*)&h;
}
__device__ __forceinline__ uint32_t pack2(float a, float b) {
    __nv_bfloat162 h;
    h.x = __float2bfloat16_rn(a);
    h.y = __float2bfloat16_rn(b);
    return *(uint32_t*)&h;
}

// split 8 fp32 (2 float4) -> hi uint4 + lo uint4
__device__ __forceinline__ void split8(float4 v0, float4 v1, uint4& h, uint4& l) {
    float r0, r1, r2, r3, r4, r5, r6, r7;
    h.x = pack_hi2(v0.x, v0.y, r0, r1);
    h.y = pack_hi2(v0.z, v0.w, r2, r3);
    h.z = pack_hi2(v1.x, v1.y, r4, r5);
    h.w = pack_hi2(v1.z, v1.w, r6, r7);
    l.x = pack2(r0, r1); l.y = pack2(r2, r3);
    l.z = pack2(r4, r5); l.w = pack2(r6, r7);
}

// ============================================================
// NT bf16x3 tensor-core GEMM with ldmatrix fragment loads.
// C[M,N] = A[M,K] * B[N,K]^T (+ bias / residual per MODE).
// Batched via blockIdx.z. M,N %128==0, K %32==0.
// ============================================================
template <int MODE>
__global__ __launch_bounds__(NTHR, 1)
void ld_nt3(const float* __restrict__ A, const float* __restrict__ Bw,
            const float* __restrict__ aux, float* __restrict__ C,
            int M, int N, int K,
            long sA, long sB, long sAux, long sC)
{
    extern __shared__ __align__(128) char smem[];
    const uint32_t sbase = smem_u32(smem);

    const int bz = blockIdx.z;
    A  += (long)bz * sA;
    Bw += (long)bz * sB;
    C  += (long)bz * sC;
    const float* R = aux ? aux + (long)bz * sAux : (const float*)0;

    const int m0 = blockIdx.y * BM;
    const int n0 = blockIdx.x * BN;
    const int tid  = threadIdx.x;
    const int wid  = tid >> 5;
    const int lane = tid & 31;
    const int g = lane >> 2;       // 0..7
    const int t = lane & 3;        // 0..3
    const int warp_m = wid & 1;    // 0..1
    const int warp_n = wid >> 1;   // 0..3

    // ldmatrix lane roles
    const int quad = lane >> 3;            // 0..3
    const int lr8  = lane & 7;             // 0..7
    const int rq   = (quad & 1) * 8 + lr8; // row within 16-row block
    const int cq   = quad >> 1;            // k-chunk sub (0/1)

    // loader: unit u = tid + i*256; row = u>>2 (0..127), c = u&3 (16B chunk)
    const int lrow = tid >> 2;       // 0..63 (+64 for i=1)
    const int lc   = tid & 3;

    float acc[4][4][4];
    #pragma unroll
    for (int mf = 0; mf < 4; mf++)
        #pragma unroll
        for (int nf = 0; nf < 4; nf++)
            #pragma unroll
            for (int r = 0; r < 4; r++) acc[mf][nf][r] = 0.f;

    float4 pa[4], pb[4];   // 2 units x 2 float4 each for A and B

    // ---- prefetch tile 0 ----
    #pragma unroll
    for (int i = 0; i < 2; i++) {
        const int row = lrow + i * 64;
        const float* ga = A  + (long)(m0 + row) * K + lc * 8;
        const float* gb = Bw + (long)(n0 + row) * K + lc * 8;
        pa[2*i]   = *(const float4*)ga;
        pa[2*i+1] = *(const float4*)(ga + 4);
        pb[2*i]   = *(const float4*)gb;
        pb[2*i+1] = *(const float4*)(gb + 4);
    }
    {
        char* aHi = smem;
        char* aLo = smem + TILE_B;
        char* bHi = smem + 2 * TILE_B;
        char* bLo = smem + 3 * TILE_B;
        #pragma unroll
        for (int i = 0; i < 2; i++) {
            const int row = lrow + i * 64;
            const uint32_t off = SWZ(row, lc);
            uint4 h, l;
            split8(pa[2*i], pa[2*i+1], h, l);
            *(uint4*)(aHi + off) = h;
            *(uint4*)(aLo + off) = l;
            split8(pb[2*i], pb[2*i+1], h, l);
            *(uint4*)(bHi + off) = h;
            *(uint4*)(bLo + off) = l;
        }
    }

    const int KT = K / BK;
    int buf = 0;
    for (int kt = 0; kt < KT; kt++) {
        __syncthreads();
        if (kt + 1 < KT) {
            const int k0 = (kt + 1) * BK;
            #pragma unroll
            for (int i = 0; i < 2; i++) {
                const int row = lrow + i * 64;
                const float* ga = A  + (long)(m0 + row) * K + k0 + lc * 8;
                const float* gb = Bw + (long)(n0 + row) * K + k0 + lc * 8;
                pa[2*i]   = *(const float4*)ga;
                pa[2*i+1] = *(const float4*)(ga + 4);
                pb[2*i]   = *(const float4*)gb;
                pb[2*i+1] = *(const float4*)(gb + 4);
            }
        }

        const uint32_t aHiB = sbase + buf * STAGE_B;
        const uint32_t aLoB = aHiB + TILE_B;
        const uint32_t bHiB = aHiB + 2 * TILE_B;
        const uint32_t bLoB = aHiB + 3 * TILE_B;

        #pragma unroll
        for (int ks = 0; ks < 2; ks++) {
            const int ck = ks * 2 + cq;
            uint32_t ah[4][4], al[4][4], bh[4][2], bl[4][2];
            #pragma unroll
            for (int mf = 0; mf < 4; mf++) {
                const int row = warp_m * 64 + mf * 16 + rq;
                const uint32_t off = SWZ(row, ck);
                ldsm4(ah[mf][0], ah[mf][1], ah[mf][2], ah[mf][3], aHiB + off);
                ldsm4(al[mf][0], al[mf][1], al[mf][2], al[mf][3], aLoB + off);
            }
            #pragma unroll
            for (int p = 0; p < 2; p++) {
                const int row = warp_n * 32 + p * 16 + rq;
                const uint32_t off = SWZ(row, ck);
                uint32_t q0, q1, q2, q3;
                ldsm4(q0, q1, q2, q3, bHiB + off);
                bh[2*p][0] = q0; bh[2*p+1][0] = q1;
                bh[2*p][1] = q2; bh[2*p+1][1] = q3;
                ldsm4(q0, q1, q2, q3, bLoB + off);
                bl[2*p][0] = q0; bl[2*p+1][0] = q1;
                bl[2*p][1] = q2; bl[2*p+1][1] = q3;
            }
            #pragma unroll
            for (int mf = 0; mf < 4; mf++)
                #pragma unroll
                for (int nf = 0; nf < 4; nf++) {
                    mma_bf16(acc[mf][nf], ah[mf][0], ah[mf][1], ah[mf][2], ah[mf][3],
                             bh[nf][0], bh[nf][1]);
                    mma_bf16(acc[mf][nf], ah[mf][0], ah[mf][1], ah[mf][2], ah[mf][3],
                             bl[nf][0], bl[nf][1]);
                    mma_bf16(acc[mf][nf], al[mf][0], al[mf][1], al[mf][2], al[mf][3],
                             bh[nf][0], bh[nf][1]);
                }
        }

        if (kt + 1 < KT) {
            buf ^= 1;
            char* aHi = smem + buf * STAGE_B;
            char* aLo = aHi + TILE_B;
            char* bHi = aHi + 2 * TILE_B;
            char* bLo = aHi + 3 * TILE_B;
            #pragma unroll
            for (int i = 0; i < 2; i++) {
                const int row = lrow + i * 64;
                const uint32_t off = SWZ(row, lc);
                uint4 h, l;
                split8(pa[2*i], pa[2*i+1], h, l);
                *(uint4*)(aHi + off) = h;
                *(uint4*)(aLo + off) = l;
                split8(pb[2*i], pb[2*i+1], h, l);
                *(uint4*)(bHi + off) = h;
                *(uint4*)(bLo + off) = l;
            }
        }
    }

    // ---------------- epilogue ----------------
    if (MODE == MODE_TBIAS) {
        // transposed per-batch store: C[b][col][s]
        const long cbase = (long)(m0 >> 12) * DD * SS;
        const int  s0    = (m0 & (SS - 1)) + warp_m * 64;
        #pragma unroll
        for (int nf = 0; nf < 4; nf++) {
            const int col = warp_n * 32 + nf * 8 + t * 2;
            const float b0 = aux[n0 + col];
            const float b1 = aux[n0 + col + 1];
            #pragma unroll
            for (int mf = 0; mf < 4; mf++) {
                const int srow = s0 + mf * 16 + g;
                float* c0 = C + cbase + (long)(n0 + col) * SS + srow;
                float* c1 = C + cbase + (long)(n0 + col + 1) * SS + srow;
                c0[0] = acc[mf][nf][0] + b0;
                c1[0] = acc[mf][nf][1] + b1;
                c0[8] = acc[mf][nf][2] + b0;
                c1[8] = acc[mf][nf][3] + b1;
            }
        }
    } else {
        #pragma unroll
        for (int nf = 0; nf < 4; nf++) {
            const int col = n0 + warp_n * 32 + nf * 8 + t * 2;
            float b0 = 0.f, b1 = 0.f;
            if (MODE == MODE_BIAS) { b0 = aux[col]; b1 = aux[col + 1]; }
            #pragma unroll
            for (int mf = 0; mf < 4; mf++) {
                const int row0 = m0 + warp_m * 64 + mf * 16 + g;
                float r00 = b0, r01 = b1, r10 = b0, r11 = b1;
                if (MODE == MODE_RES) {
                    float2 rr0 = *(const float2*)(R + (long)row0 * N + col);
                    float2 rr1 = *(const float2*)(R + (long)(row0 + 8) * N + col);
                    r00 = rr0.x; r01 = rr0.y; r10 = rr1.x; r11 = rr1.y;
                }
                float2 v0 = make_float2(acc[mf][nf][0] + r00, acc[mf][nf][1] + r01);
                float2 v1 = make_float2(acc[mf][nf][2] + r10, acc[mf][nf][3] + r11);
                *(float2*)(C + (long)row0 * N + col)       = v0;
                *(float2*)(C + (long)(row0 + 8) * N + col) = v1;
            }
        }
    }
}

// ============================================================
// Row softmax over SS=4096 columns. One block (256 thr) per row.
// ============================================================
__global__ __launch_bounds__(256)
void softmax_rows(float* __restrict__ attn)
{
    float* p = attn + (size_t)blockIdx.x * SS;
    const int tid = threadIdx.x;

    float4 v[4];
    float mx = -INFINITY;
    #pragma unroll
    for (int i = 0; i < 4; i++) {
        v[i] = *(float4*)(p + (tid + i * 256) * 4);
        mx = fmaxf(fmaxf(fmaxf(v[i].x, v[i].y), fmaxf(v[i].z, v[i].w)), mx);
    }
    __shared__ float red[8];
    #pragma unroll
    for (int o = 16; o; o >>= 1) mx = fmaxf(mx, __shfl_xor_sync(0xffffffffu, mx, o));
    if ((tid & 31) == 0) red[tid >> 5] = mx;
    __syncthreads();
    float m = red[0];
    #pragma unroll
    for (int i = 1; i < 8; i++) m = fmaxf(m, red[i]);
    __syncthreads();

    float s = 0.f;
    #pragma unroll
    for (int i = 0; i < 4; i++) {
        v[i].x = __expf(v[i].x - m); v[i].y = __expf(v[i].y - m);
        v[i].z = __expf(v[i].z - m); v[i].w = __expf(v[i].w - m);
        s += v[i].x + v[i].y + v[i].z + v[i].w;
    }
    #pragma unroll
    for (int o = 16; o; o >>= 1) s += __shfl_xor_sync(0xffffffffu, s, o);
    if ((tid & 31) == 0) red[tid >> 5] = s;
    __syncthreads();
    float tot = 0.f;
    #pragma unroll
    for (int i = 0; i < 8; i++) tot += red[i];
    const float inv = 1.f / tot;

    #pragma unroll
    for (int i = 0; i < 4; i++) {
        v[i].x *= inv; v[i].y *= inv; v[i].z *= inv; v[i].w *= inv;
        *(float4*)(p + (tid + i * 256) * 4) = v[i];
    }
}

// ============================================================
extern "C" void kernel_launch(void* const* d_in, const int* in_sizes, int n_in,
                              void* d_out, int out_size)
{
    const float* x   = (const float*)d_in[0];
    const float* y   = (const float*)d_in[1];
    const float* Wq  = (const float*)d_in[2];
    const float* bq  = (const float*)d_in[3];
    const float* Wqv = (const float*)d_in[4];
    const float* bqv = (const float*)d_in[5];
    const float* Wk  = (const float*)d_in[6];
    const float* bk  = (const float*)d_in[7];
    const float* Wkv = (const float*)d_in[8];
    const float* bkv = (const float*)d_in[9];
    const float* Wf  = (const float*)d_in[10];
    const float* bf  = (const float*)d_in[11];
    float* out = (float*)d_out;

    float *q, *qv, *k, *kvT, *o, *attn;
    cudaGetSymbolAddress((void**)&q,    g_q);
    cudaGetSymbolAddress((void**)&qv,   g_qv);
    cudaGetSymbolAddress((void**)&k,    g_k);
    cudaGetSymbolAddress((void**)&kvT,  g_kvT);
    cudaGetSymbolAddress((void**)&o,    g_out);
    cudaGetSymbolAddress((void**)&attn, g_attn);

    cudaFuncSetAttribute(ld_nt3<MODE_BIAS>,  cudaFuncAttributeMaxDynamicSharedMemorySize, SMEM_BYTES);
    cudaFuncSetAttribute(ld_nt3<MODE_TBIAS>, cudaFuncAttributeMaxDynamicSharedMemorySize, SMEM_BYTES);
    cudaFuncSetAttribute(ld_nt3<MODE_PLAIN>, cudaFuncAttributeMaxDynamicSharedMemorySize, SMEM_BYTES);
    cudaFuncSetAttribute(ld_nt3<MODE_RES>,   cudaFuncAttributeMaxDynamicSharedMemorySize, SMEM_BYTES);

    dim3 thr(NTHR);

    // 1-4. projections: [16384,512] = [16384,512] x [512,512]^T
    {
        dim3 grid(DD / BN, MTOT / BM, 1);
        ld_nt3<MODE_BIAS> <<<grid, thr, SMEM_BYTES>>>(x, Wq,  bq,  q,   MTOT, DD, DD, 0, 0, 0, 0);
        ld_nt3<MODE_BIAS> <<<grid, thr, SMEM_BYTES>>>(x, Wqv, bqv, qv,  MTOT, DD, DD, 0, 0, 0, 0);
        ld_nt3<MODE_BIAS> <<<grid, thr, SMEM_BYTES>>>(y, Wk,  bk,  k,   MTOT, DD, DD, 0, 0, 0, 0);
        ld_nt3<MODE_TBIAS><<<grid, thr, SMEM_BYTES>>>(y, Wkv, bkv, kvT, MTOT, DD, DD, 0, 0, 0, 0);
    }

    // 5. scores = q @ k^T per batch: [4096,4096], K=512
    {
        dim3 grid(SS / BN, SS / BM, BB);
        ld_nt3<MODE_PLAIN><<<grid, thr, SMEM_BYTES>>>(q, k, nullptr, attn, SS, SS, DD,
                                                      (long)SS * DD, (long)SS * DD, 0, (long)SS * SS);
    }

    // 6. softmax over rows
    softmax_rows<<<BB * SS, 256>>>(attn);

    // 7. o = attn @ kvT^T + qv per batch: [4096,512], K=4096 (NT form)
    {
        dim3 grid(DD / BN, SS / BM, BB);
        ld_nt3<MODE_RES><<<grid, thr, SMEM_BYTES>>>(attn, kvT, qv, o, SS, DD, SS,
                                                    (long)SS * SS, (long)DD * SS,
                                                    (long)SS * DD, (long)SS * DD);
    }

    // 8. final = o @ Wf^T + bf: [16384,512]
    {
        dim3 grid(DD / BN, MTOT / BM, 1);
        ld_nt3<MODE_BIAS><<<grid, thr, SMEM_BYTES>>>(o, Wf, bf, out, MTOT, DD, DD, 0, 0, 0, 0);
    }
}

// round 11
// speedup vs baseline: 2.6828x; 1.2333x over previous
#include <cuda_runtime.h>
#include <cuda_bf16.h>
#include <math.h>
#include <stdint.h>

// Problem constants
#define BB 4
#define SS 4096
#define DD 512
#define MTOT (BB*SS)          // 16384 flattened rows

// Tiling
#define BM 128
#define BN 128
#define BK 32
#define NTHR 256              // 8 warps: 2 (M) x 4 (N), warp tile 64x32
#define STAGES 3

// smem: unpadded bf16 tiles 128 rows x 32 cols = 64B/row, XOR-swizzled chunks
#define TILE_B   (128 * 64)       // 8192 bytes
#define STAGE_B  (4 * TILE_B)     // Ahi, Alo, Bhi, Blo = 32768
#define SMEM_BYTES (STAGES * STAGE_B)  // 98304

// swizzled byte offset of 16B chunk (row, c), c = k-chunk 0..3
#define SWZ(row, c) ((uint32_t)((row) * 64 + ((((c) ^ (((row) >> 1) & 3))) << 4)))

// epilogue modes
#define MODE_BIAS_F32    0   // C_f32 = acc + bias      (final output)
#define MODE_TBIAS_SPLIT 1   // Ch/Cl = acc + bias, transposed [D][S] store (kvT)
#define MODE_PLAIN_F32   2   // C_f32 = acc             (attn logits)
#define MODE_RES_SPLIT   3   // Ch/Cl = acc + R         (o = AV + qv)
#define MODE_BIAS_SPLIT  4   // Ch/Cl = acc + bias      (q, k)

typedef __nv_bfloat16 bf16;

// -------- scratch (device globals: allocation-free rule) --------
__device__ bf16  g_xs_h[MTOT * DD], g_xs_l[MTOT * DD];
__device__ bf16  g_ys_h[MTOT * DD], g_ys_l[MTOT * DD];
__device__ bf16  g_Wq_h [DD * DD], g_Wq_l [DD * DD];
__device__ bf16  g_Wqv_h[DD * DD], g_Wqv_l[DD * DD];
__device__ bf16  g_Wk_h [DD * DD], g_Wk_l [DD * DD];
__device__ bf16  g_Wkv_h[DD * DD], g_Wkv_l[DD * DD];
__device__ bf16  g_Wf_h [DD * DD], g_Wf_l [DD * DD];
__device__ bf16  g_q_h [MTOT * DD], g_q_l [MTOT * DD];
__device__ bf16  g_k_h [MTOT * DD], g_k_l [MTOT * DD];
__device__ bf16  g_kvT_h[MTOT * DD], g_kvT_l[MTOT * DD];   // [B][D][S]
__device__ bf16  g_o_h [MTOT * DD], g_o_l [MTOT * DD];
__device__ float g_qv [MTOT * DD];
__device__ float g_attn[(size_t)BB * SS * SS];             // 256 MB logits
__device__ bf16  g_attn_h[(size_t)BB * SS * SS];           // 128 MB
__device__ bf16  g_attn_l[(size_t)BB * SS * SS];           // 128 MB

__device__ __forceinline__ uint32_t smem_u32(const void* p) {
    uint32_t a;
    asm("{ .reg .u64 t; cvta.to.shared.u64 t, %1; cvt.u32.u64 %0, t; }"
        : "=r"(a) : "l"(p));
    return a;
}

__device__ __forceinline__ void mma_bf16(float c[4],
                                         uint32_t a0, uint32_t a1, uint32_t a2, uint32_t a3,
                                         uint32_t b0, uint32_t b1) {
    asm volatile(
        "mma.sync.aligned.m16n8k16.row.col.f32.bf16.bf16.f32 "
        "{%0,%1,%2,%3}, {%4,%5,%6,%7}, {%8,%9}, {%0,%1,%2,%3};\n"
        : "+f"(c[0]), "+f"(c[1]), "+f"(c[2]), "+f"(c[3])
        : "r"(a0), "r"(a1), "r"(a2), "r"(a3), "r"(b0), "r"(b1));
}

__device__ __forceinline__ void ldsm4(uint32_t& r0, uint32_t& r1, uint32_t& r2, uint32_t& r3,
                                      uint32_t addr) {
    asm volatile("ldmatrix.sync.aligned.m8n8.x4.shared.b16 {%0,%1,%2,%3}, [%4];"
                 : "=r"(r0), "=r"(r1), "=r"(r2), "=r"(r3) : "r"(addr));
}

#define CP16(sp, gp) \
    asm volatile("cp.async.cg.shared.global [%0], [%1], 16;" :: "r"(sp), "l"(gp))
#define CP_COMMIT() asm volatile("cp.async.commit_group;" ::: "memory")
#define CP_WAIT2()  asm volatile("cp.async.wait_group 2;" ::: "memory")

// split float pair -> hi bf162 word + lo bf162 word
__device__ __forceinline__ void split2(float a, float b, uint32_t& h, uint32_t& l) {
    __nv_bfloat162 hh, ll;
    hh.x = __float2bfloat16_rn(a);
    hh.y = __float2bfloat16_rn(b);
    ll.x = __float2bfloat16_rn(a - __bfloat162float(hh.x));
    ll.y = __float2bfloat16_rn(b - __bfloat162float(hh.y));
    h = *(uint32_t*)&hh;
    l = *(uint32_t*)&ll;
}

// ============================================================
// presplit: fp32 -> bf16 hi + bf16 lo, elementwise
// ============================================================
__global__ __launch_bounds__(256)
void presplit(const float* __restrict__ in, bf16* __restrict__ hi,
              bf16* __restrict__ lo, int n)
{
    const int i = (blockIdx.x * 256 + threadIdx.x) * 4;
    if (i >= n) return;
    float4 v = *(const float4*)(in + i);
    uint32_t h0, l0, h1, l1;
    split2(v.x, v.y, h0, l0);
    split2(v.z, v.w, h1, l1);
    uint2 hh = make_uint2(h0, h1), ll = make_uint2(l0, l1);
    *(uint2*)(hi + i) = hh;
    *(uint2*)(lo + i) = ll;
}

// ============================================================
// NT bf16x3 GEMM, cp.async 3-stage pipeline, ldmatrix frags.
// C[M,N] = A[M,K] * B[N,K]^T, inputs pre-split hi/lo bf16.
// Batched via blockIdx.z. M,N %128==0, K %32==0.
// ============================================================
template <int MODE>
__global__ __launch_bounds__(NTHR, 2)
void cp_nt3(const bf16* __restrict__ Ah, const bf16* __restrict__ Al,
            const bf16* __restrict__ Bh, const bf16* __restrict__ Bl,
            const float* __restrict__ aux,      // bias or residual R
            float* __restrict__ C, bf16* __restrict__ Ch, bf16* __restrict__ Cl,
            int M, int N, int K,
            long sA, long sB, long sAux, long sC)
{
    extern __shared__ __align__(128) char smem[];
    const uint32_t sbase = smem_u32(smem);

    const int bz = blockIdx.z;
    Ah += (long)bz * sA;  Al += (long)bz * sA;
    Bh += (long)bz * sB;  Bl += (long)bz * sB;
    const float* R = aux ? aux + (long)bz * sAux : (const float*)0;
    if (C)  C  += (long)bz * sC;
    if (Ch) { Ch += (long)bz * sC; Cl += (long)bz * sC; }

    const int m0 = blockIdx.y * BM;
    const int n0 = blockIdx.x * BN;
    const int tid  = threadIdx.x;
    const int wid  = tid >> 5;
    const int lane = tid & 31;
    const int g = lane >> 2;       // 0..7
    const int t = lane & 3;        // 0..3
    const int warp_m = wid & 1;    // 0..1
    const int warp_n = wid >> 1;   // 0..3

    // ldmatrix lane roles
    const int quad = lane >> 3;
    const int lr8  = lane & 7;
    const int rq   = (quad & 1) * 8 + lr8;
    const int cq   = quad >> 1;

    // loader roles: j 0..7 -> tile j>>1, row (tid>>2)+64*(j&1), chunk tid&3
    const int lrow  = tid >> 2;
    const int lchnk = tid & 3;
    const bf16* tb[4] = { Ah + (long)m0 * K, Al + (long)m0 * K,
                          Bh + (long)n0 * K, Bl + (long)n0 * K };

    float acc[4][4][4];
    #pragma unroll
    for (int mf = 0; mf < 4; mf++)
        #pragma unroll
        for (int nf = 0; nf < 4; nf++)
            #pragma unroll
            for (int r = 0; r < 4; r++) acc[mf][nf][r] = 0.f;

    const int KT = K / BK;

    // issue helper expanded inline (stage s, k-tile kt)
    #define ISSUE_STAGE(kt_, s_) do {                                          \
        const int k0_ = (kt_) * BK;                                            \
        _Pragma("unroll")                                                      \
        for (int j = 0; j < 8; j++) {                                          \
            const int tile_ = j >> 1;                                          \
            const int row_  = lrow + 64 * (j & 1);                             \
            const bf16* gp_ = tb[tile_] + (long)row_ * K + k0_ + lchnk * 8;    \
            uint32_t sp_ = sbase + (s_) * STAGE_B + tile_ * TILE_B             \
                         + SWZ(row_, lchnk);                                   \
            CP16(sp_, gp_);                                                    \
        }                                                                      \
    } while (0)

    ISSUE_STAGE(0, 0); CP_COMMIT();
    ISSUE_STAGE(1, 1); CP_COMMIT();

    for (int kt = 0; kt < KT; kt++) {
        if (kt + 2 < KT) ISSUE_STAGE(kt + 2, (kt + 2) % STAGES);
        CP_COMMIT();                 // always commit (empty group on tail)
        CP_WAIT2();
        __syncthreads();

        const uint32_t stg = sbase + (kt % STAGES) * STAGE_B;
        const uint32_t aHiB = stg;
        const uint32_t aLoB = stg + TILE_B;
        const uint32_t bHiB = stg + 2 * TILE_B;
        const uint32_t bLoB = stg + 3 * TILE_B;

        #pragma unroll
        for (int ks = 0; ks < 2; ks++) {
            const int ck = ks * 2 + cq;
            uint32_t ah[4][4], al[4][4], bh[4][2], bl[4][2];
            #pragma unroll
            for (int mf = 0; mf < 4; mf++) {
                const int row = warp_m * 64 + mf * 16 + rq;
                const uint32_t off = SWZ(row, ck);
                ldsm4(ah[mf][0], ah[mf][1], ah[mf][2], ah[mf][3], aHiB + off);
                ldsm4(al[mf][0], al[mf][1], al[mf][2], al[mf][3], aLoB + off);
            }
            #pragma unroll
            for (int p = 0; p < 2; p++) {
                const int row = warp_n * 32 + p * 16 + rq;
                const uint32_t off = SWZ(row, ck);
                uint32_t q0, q1, q2, q3;
                ldsm4(q0, q1, q2, q3, bHiB + off);
                bh[2*p][0] = q0; bh[2*p+1][0] = q1;
                bh[2*p][1] = q2; bh[2*p+1][1] = q3;
                ldsm4(q0, q1, q2, q3, bLoB + off);
                bl[2*p][0] = q0; bl[2*p+1][0] = q1;
                bl[2*p][1] = q2; bl[2*p+1][1] = q3;
            }
            #pragma unroll
            for (int mf = 0; mf < 4; mf++)
                #pragma unroll
                for (int nf = 0; nf < 4; nf++) {
                    mma_bf16(acc[mf][nf], ah[mf][0], ah[mf][1], ah[mf][2], ah[mf][3],
                             bh[nf][0], bh[nf][1]);
                    mma_bf16(acc[mf][nf], ah[mf][0], ah[mf][1], ah[mf][2], ah[mf][3],
                             bl[nf][0], bl[nf][1]);
                    mma_bf16(acc[mf][nf], al[mf][0], al[mf][1], al[mf][2], al[mf][3],
                             bh[nf][0], bh[nf][1]);
                }
        }
        __syncthreads();
    }

    // ---------------- epilogue ----------------
    if (MODE == MODE_TBIAS_SPLIT) {
        const long cbase = (long)(m0 >> 12) * DD * SS;
        const int  s0    = (m0 & (SS - 1)) + warp_m * 64;
        #pragma unroll
        for (int nf = 0; nf < 4; nf++) {
            const int col = warp_n * 32 + nf * 8 + t * 2;
            const float b0 = aux[n0 + col];
            const float b1 = aux[n0 + col + 1];
            #pragma unroll
            for (int mf = 0; mf < 4; mf++) {
                const int srow = s0 + mf * 16 + g;
                const long i00 = cbase + (long)(n0 + col) * SS + srow;
                const long i01 = cbase + (long)(n0 + col + 1) * SS + srow;
                float v00 = acc[mf][nf][0] + b0, v01 = acc[mf][nf][1] + b1;
                float v10 = acc[mf][nf][2] + b0, v11 = acc[mf][nf][3] + b1;
                bf16 h;
                h = __float2bfloat16_rn(v00); Ch[i00]     = h; Cl[i00]     = __float2bfloat16_rn(v00 - __bfloat162float(h));
                h = __float2bfloat16_rn(v01); Ch[i01]     = h; Cl[i01]     = __float2bfloat16_rn(v01 - __bfloat162float(h));
                h = __float2bfloat16_rn(v10); Ch[i00 + 8] = h; Cl[i00 + 8] = __float2bfloat16_rn(v10 - __bfloat162float(h));
                h = __float2bfloat16_rn(v11); Ch[i01 + 8] = h; Cl[i01 + 8] = __float2bfloat16_rn(v11 - __bfloat162float(h));
            }
        }
    } else {
        #pragma unroll
        for (int nf = 0; nf < 4; nf++) {
            const int col = n0 + warp_n * 32 + nf * 8 + t * 2;
            float b0 = 0.f, b1 = 0.f;
            if (MODE == MODE_BIAS_F32 || MODE == MODE_BIAS_SPLIT) {
                b0 = aux[col]; b1 = aux[col + 1];
            }
            #pragma unroll
            for (int mf = 0; mf < 4; mf++) {
                const int row0 = m0 + warp_m * 64 + mf * 16 + g;
                float r00 = b0, r01 = b1, r10 = b0, r11 = b1;
                if (MODE == MODE_RES_SPLIT) {
                    float2 rr0 = *(const float2*)(R + (long)row0 * N + col);
                    float2 rr1 = *(const float2*)(R + (long)(row0 + 8) * N + col);
                    r00 = rr0.x; r01 = rr0.y; r10 = rr1.x; r11 = rr1.y;
                }
                const float v00 = acc[mf][nf][0] + r00;
                const float v01 = acc[mf][nf][1] + r01;
                const float v10 = acc[mf][nf][2] + r10;
                const float v11 = acc[mf][nf][3] + r11;
                if (MODE == MODE_BIAS_F32 || MODE == MODE_PLAIN_F32) {
                    *(float2*)(C + (long)row0 * N + col)       = make_float2(v00, v01);
                    *(float2*)(C + (long)(row0 + 8) * N + col) = make_float2(v10, v11);
                } else {
                    uint32_t h0, l0, h1, l1;
                    split2(v00, v01, h0, l0);
                    split2(v10, v11, h1, l1);
                    *(uint32_t*)(Ch + (long)row0 * N + col)       = h0;
                    *(uint32_t*)(Cl + (long)row0 * N + col)       = l0;
                    *(uint32_t*)(Ch + (long)(row0 + 8) * N + col) = h1;
                    *(uint32_t*)(Cl + (long)(row0 + 8) * N + col) = l1;
                }
            }
        }
    }
}

// ============================================================
// Row softmax over SS=4096 columns -> bf16 hi/lo output.
// One block (256 thr) per row.
// ============================================================
__global__ __launch_bounds__(256)
void softmax_split(const float* __restrict__ attn,
                   bf16* __restrict__ ph, bf16* __restrict__ pl)
{
    const size_t rb = (size_t)blockIdx.x * SS;
    const float* p = attn + rb;
    const int tid = threadIdx.x;

    float4 v[4];
    float mx = -INFINITY;
    #pragma unroll
    for (int i = 0; i < 4; i++) {
        v[i] = *(const float4*)(p + (tid + i * 256) * 4);
        mx = fmaxf(fmaxf(fmaxf(v[i].x, v[i].y), fmaxf(v[i].z, v[i].w)), mx);
    }
    __shared__ float red[8];
    #pragma unroll
    for (int o = 16; o; o >>= 1) mx = fmaxf(mx, __shfl_xor_sync(0xffffffffu, mx, o));
    if ((tid & 31) == 0) red[tid >> 5] = mx;
    __syncthreads();
    float m = red[0];
    #pragma unroll
    for (int i = 1; i < 8; i++) m = fmaxf(m, red[i]);
    __syncthreads();

    float s = 0.f;
    #pragma unroll
    for (int i = 0; i < 4; i++) {
        v[i].x = __expf(v[i].x - m); v[i].y = __expf(v[i].y - m);
        v[i].z = __expf(v[i].z - m); v[i].w = __expf(v[i].w - m);
        s += v[i].x + v[i].y + v[i].z + v[i].w;
    }
    #pragma unroll
    for (int o = 16; o; o >>= 1) s += __shfl_xor_sync(0xffffffffu, s, o);
    if ((tid & 31) == 0) red[tid >> 5] = s;
    __syncthreads();
    float tot = 0.f;
    #pragma unroll
    for (int i = 0; i < 8; i++) tot += red[i];
    const float inv = 1.f / tot;

    #pragma unroll
    for (int i = 0; i < 4; i++) {
        const float p0 = v[i].x * inv, p1 = v[i].y * inv;
        const float p2 = v[i].z * inv, p3 = v[i].w * inv;
        uint32_t h0, l0, h1, l1;
        split2(p0, p1, h0, l0);
        split2(p2, p3, h1, l1);
        const size_t idx = rb + (size_t)(tid + i * 256) * 4;
        *(uint2*)(ph + idx) = make_uint2(h0, h1);
        *(uint2*)(pl + idx) = make_uint2(l0, l1);
    }
}

// ============================================================
extern "C" void kernel_launch(void* const* d_in, const int* in_sizes, int n_in,
                              void* d_out, int out_size)
{
    const float* x   = (const float*)d_in[0];
    const float* y   = (const float*)d_in[1];
    const float* Wq  = (const float*)d_in[2];
    const float* bq  = (const float*)d_in[3];
    const float* Wqv = (const float*)d_in[4];
    const float* bqv = (const float*)d_in[5];
    const float* Wk  = (const float*)d_in[6];
    const float* bk  = (const float*)d_in[7];
    const float* Wkv = (const float*)d_in[8];
    const float* bkv = (const float*)d_in[9];
    const float* Wf  = (const float*)d_in[10];
    const float* bf  = (const float*)d_in[11];
    float* out = (float*)d_out;

    bf16 *xs_h, *xs_l, *ys_h, *ys_l;
    bf16 *Wq_h, *Wq_l, *Wqv_h, *Wqv_l, *Wk_h, *Wk_l, *Wkv_h, *Wkv_l, *Wf_h, *Wf_l;
    bf16 *q_h, *q_l, *k_h, *k_l, *kvT_h, *kvT_l, *o_h, *o_l, *at_h, *at_l;
    float *qv, *attn;
    cudaGetSymbolAddress((void**)&xs_h,  g_xs_h);  cudaGetSymbolAddress((void**)&xs_l,  g_xs_l);
    cudaGetSymbolAddress((void**)&ys_h,  g_ys_h);  cudaGetSymbolAddress((void**)&ys_l,  g_ys_l);
    cudaGetSymbolAddress((void**)&Wq_h,  g_Wq_h);  cudaGetSymbolAddress((void**)&Wq_l,  g_Wq_l);
    cudaGetSymbolAddress((void**)&Wqv_h, g_Wqv_h); cudaGetSymbolAddress((void**)&Wqv_l, g_Wqv_l);
    cudaGetSymbolAddress((void**)&Wk_h,  g_Wk_h);  cudaGetSymbolAddress((void**)&Wk_l,  g_Wk_l);
    cudaGetSymbolAddress((void**)&Wkv_h, g_Wkv_h); cudaGetSymbolAddress((void**)&Wkv_l, g_Wkv_l);
    cudaGetSymbolAddress((void**)&Wf_h,  g_Wf_h);  cudaGetSymbolAddress((void**)&Wf_l,  g_Wf_l);
    cudaGetSymbolAddress((void**)&q_h,   g_q_h);   cudaGetSymbolAddress((void**)&q_l,   g_q_l);
    cudaGetSymbolAddress((void**)&k_h,   g_k_h);   cudaGetSymbolAddress((void**)&k_l,   g_k_l);
    cudaGetSymbolAddress((void**)&kvT_h, g_kvT_h); cudaGetSymbolAddress((void**)&kvT_l, g_kvT_l);
    cudaGetSymbolAddress((void**)&o_h,   g_o_h);   cudaGetSymbolAddress((void**)&o_l,   g_o_l);
    cudaGetSymbolAddress((void**)&at_h,  g_attn_h);cudaGetSymbolAddress((void**)&at_l,  g_attn_l);
    cudaGetSymbolAddress((void**)&qv,    g_qv);
    cudaGetSymbolAddress((void**)&attn,  g_attn);

    cudaFuncSetAttribute(cp_nt3<MODE_BIAS_F32>,    cudaFuncAttributeMaxDynamicSharedMemorySize, SMEM_BYTES);
    cudaFuncSetAttribute(cp_nt3<MODE_TBIAS_SPLIT>, cudaFuncAttributeMaxDynamicSharedMemorySize, SMEM_BYTES);
    cudaFuncSetAttribute(cp_nt3<MODE_PLAIN_F32>,   cudaFuncAttributeMaxDynamicSharedMemorySize, SMEM_BYTES);
    cudaFuncSetAttribute(cp_nt3<MODE_RES_SPLIT>,   cudaFuncAttributeMaxDynamicSharedMemorySize, SMEM_BYTES);
    cudaFuncSetAttribute(cp_nt3<MODE_BIAS_SPLIT>,  cudaFuncAttributeMaxDynamicSharedMemorySize, SMEM_BYTES);

    dim3 thr(NTHR);

    // 0. presplit inputs and weights to bf16 hi/lo
    presplit<<<MTOT * DD / 1024, 256>>>(x, xs_h, xs_l, MTOT * DD);
    presplit<<<MTOT * DD / 1024, 256>>>(y, ys_h, ys_l, MTOT * DD);
    presplit<<<DD * DD / 1024, 256>>>(Wq,  Wq_h,  Wq_l,  DD * DD);
    presplit<<<DD * DD / 1024, 256>>>(Wqv, Wqv_h, Wqv_l, DD * DD);
    presplit<<<DD * DD / 1024, 256>>>(Wk,  Wk_h,  Wk_l,  DD * DD);
    presplit<<<DD * DD / 1024, 256>>>(Wkv, Wkv_h, Wkv_l, DD * DD);
    presplit<<<DD * DD / 1024, 256>>>(Wf,  Wf_h,  Wf_l,  DD * DD);

    // 1-4. projections
    {
        dim3 grid(DD / BN, MTOT / BM, 1);
        cp_nt3<MODE_BIAS_SPLIT> <<<grid, thr, SMEM_BYTES>>>(xs_h, xs_l, Wq_h,  Wq_l,  bq,  nullptr, q_h, q_l,
                                                            MTOT, DD, DD, 0, 0, 0, 0);
        cp_nt3<MODE_BIAS_F32>   <<<grid, thr, SMEM_BYTES>>>(xs_h, xs_l, Wqv_h, Wqv_l, bqv, qv, nullptr, nullptr,
                                                            MTOT, DD, DD, 0, 0, 0, 0);
        cp_nt3<MODE_BIAS_SPLIT> <<<grid, thr, SMEM_BYTES>>>(ys_h, ys_l, Wk_h,  Wk_l,  bk,  nullptr, k_h, k_l,
                                                            MTOT, DD, DD, 0, 0, 0, 0);
        cp_nt3<MODE_TBIAS_SPLIT><<<grid, thr, SMEM_BYTES>>>(ys_h, ys_l, Wkv_h, Wkv_l, bkv, nullptr, kvT_h, kvT_l,
                                                            MTOT, DD, DD, 0, 0, 0, 0);
    }

    // 5. scores = q @ k^T per batch: [4096,4096], K=512
    {
        dim3 grid(SS / BN, SS / BM, BB);
        cp_nt3<MODE_PLAIN_F32><<<grid, thr, SMEM_BYTES>>>(q_h, q_l, k_h, k_l, nullptr, attn, nullptr, nullptr,
                                                          SS, SS, DD,
                                                          (long)SS * DD, (long)SS * DD, 0, (long)SS * SS);
    }

    // 6. softmax -> bf16 hi/lo probabilities
    softmax_split<<<BB * SS, 256>>>(attn, at_h, at_l);

    // 7. o = attn @ kvT^T + qv per batch: [4096,512], K=4096 (NT form)
    {
        dim3 grid(DD / BN, SS / BM, BB);
        cp_nt3<MODE_RES_SPLIT><<<grid, thr, SMEM_BYTES>>>(at_h, at_l, kvT_h, kvT_l, qv, nullptr, o_h, o_l,
                                                          SS, DD, SS,
                                                          (long)SS * SS, (long)DD * SS,
                                                          (long)SS * DD, (long)SS * DD);
    }

    // 8. final = o @ Wf^T + bf: [16384,512]
    {
        dim3 grid(DD / BN, MTOT / BM, 1);
        cp_nt3<MODE_BIAS_F32><<<grid, thr, SMEM_BYTES>>>(o_h, o_l, Wf_h, Wf_l, bf, out, nullptr, nullptr,
                                                         MTOT, DD, DD, 0, 0, 0, 0);
    }
}